// round 1
// baseline (speedup 1.0000x reference)
#include <cuda_runtime.h>
#include <cuda_bf16.h>
#include <math.h>

// Problem dims
#define S_ 4
#define B_ 16
#define T_ 23        // L-1
#define L_ 24
#define H_ 512
#define E_ 512
#define G3 1536      // 3H
#define V_ 32000
#define ROWS 1472    // S*T*B
#define ROWS_PER_S 368

// Scratch (device globals; no runtime allocation allowed)
__device__ float g_A[ROWS * 1024];        // per-row feats: [0:512)=emb, [512:1024)=h
__device__ float g_gi[ROWS * G3];         // gi_seq
__device__ float g_gictx[64 * G3];        // ctx part of gi (+ b_ih)
__device__ float g_h[2][S_ * B_ * H_];    // double-buffered hidden state
__device__ float g_ctxlogit[64 * V_];     // agg @ fc_W[:,1024:] + fc_b

static __device__ __forceinline__ float sigmoidf_(float x) {
    return 1.0f / (1.0f + expf(-x));
}

// ---------------------------------------------------------------------------
// out[b][s][0][v] = (v==1)
__global__ void k_onehot(float* __restrict__ out) {
    long i = (long)blockIdx.x * blockDim.x + threadIdx.x;
    if (i < (long)64 * V_) {
        int p = (int)(i / V_);           // p = b*4 + s
        int v = (int)(i - (long)p * V_);
        out[(size_t)p * L_ * V_ + v] = (v == 1) ? 1.0f : 0.0f;
    }
}

// copy hidden -> g_h[0]
__global__ void k_hinit(const float* __restrict__ hidden) {
    int i = blockIdx.x * 256 + threadIdx.x;
    if (i < S_ * B_ * H_) g_h[0][i] = hidden[i];
}

// gather embeddings into g_A[row][0:512)
__global__ void k_gather(const int* __restrict__ input, const float* __restrict__ emb) {
    int row = blockIdx.x;                 // 0..1471
    int s = row / ROWS_PER_S;
    int rr = row - s * ROWS_PER_S;
    int t = rr >> 4;
    int b = rr & 15;
    int tok = input[(b * S_ + s) * L_ + t];
    const float4* src = (const float4*)(emb + (size_t)tok * E_);
    float4* dst = (float4*)(g_A + (size_t)row * 1024);
    dst[threadIdx.x] = src[threadIdx.x];  // 128 threads x float4 = 512 floats
}

// ---------------------------------------------------------------------------
// gictx[s,b,g] = sum_d ctx[s,b,d] * W_ih[s,g,512+d] + b_ih[s,g]
// one warp per (s,g); 8 warps/block
__global__ void k_ctx_gi(const float* __restrict__ hidden,
                         const float* __restrict__ agg,
                         const float* __restrict__ W_ih,
                         const float* __restrict__ b_ih) {
    int w = blockIdx.x * 8 + (threadIdx.x >> 5);
    int lane = threadIdx.x & 31;
    int s = w / G3;
    int g = w - s * G3;
    const float* ctx = (s == 0) ? agg : (hidden + (size_t)s * B_ * H_);
    const float* wrow = W_ih + ((size_t)(s * G3) + g) * 1024 + 512;
    float acc[16];
#pragma unroll
    for (int b = 0; b < 16; b++) acc[b] = 0.0f;
    for (int d = lane; d < 512; d += 32) {
        float wv = wrow[d];
#pragma unroll
        for (int b = 0; b < 16; b++) acc[b] += wv * ctx[b * 512 + d];
    }
    float res = 0.0f;
#pragma unroll
    for (int b = 0; b < 16; b++) {
        float v = acc[b];
#pragma unroll
        for (int off = 16; off; off >>= 1) v += __shfl_xor_sync(0xffffffffu, v, off);
        if (lane == b) res = v;
    }
    if (lane < 16)
        g_gictx[(size_t)(s * 16 + lane) * G3 + g] = res + b_ih[s * G3 + g];
}

// ---------------------------------------------------------------------------
// Generic C = A * B^T tiled fp32 GEMM (A: MxK lda, B: NxK ldb), mode-specific epilogue.
// BM=BN=128, BK=16, 256 threads, 8x8 per thread.
__global__ void __launch_bounds__(256) k_gemm(
    int mode,
    const float* __restrict__ Aext,
    const float* __restrict__ Bext,
    const float* __restrict__ bias,
    float* __restrict__ out) {
    int s = blockIdx.z;
    const float* A;
    const float* B;
    int lda, ldb, M, K;
    if (mode == 0) {            // gi: emb part
        A = g_A + (size_t)s * ROWS_PER_S * 1024; lda = 1024;
        B = Bext + (size_t)s * G3 * 1024;        ldb = 1024;   // W_ih[s]
        M = ROWS_PER_S; K = 512;
    } else if (mode == 1) {     // ctx_logit
        A = Aext; lda = 512;                     // output_agg (64 x 512)
        B = Bext; ldb = 1536;                    // fc_W + 1024
        M = 64; K = 512;
    } else {                    // FC main
        A = g_A; lda = 1024;
        B = Bext; ldb = 1536;                    // fc_W
        M = ROWS; K = 1024;
    }

    __shared__ float As[16][128];
    __shared__ float Bs[16][128];

    int tid = threadIdx.x;
    int m0 = blockIdx.y * 128;
    int n0 = blockIdx.x * 128;
    int trow = tid >> 4;
    int tcol = tid & 15;

    float acc[8][8];
#pragma unroll
    for (int i = 0; i < 8; i++)
#pragma unroll
        for (int j = 0; j < 8; j++) acc[i][j] = 0.0f;

    for (int k0 = 0; k0 < K; k0 += 16) {
        // load tiles: 512 float4s each for A and B; 2 per thread
#pragma unroll
        for (int it = 0; it < 2; it++) {
            int i = tid + it * 256;
            int mm = i >> 2;
            int kk = (i & 3) << 2;
            float4 av = make_float4(0.f, 0.f, 0.f, 0.f);
            if (m0 + mm < M)
                av = *(const float4*)(A + (size_t)(m0 + mm) * lda + k0 + kk);
            As[kk + 0][mm] = av.x; As[kk + 1][mm] = av.y;
            As[kk + 2][mm] = av.z; As[kk + 3][mm] = av.w;
            float4 bv = *(const float4*)(B + (size_t)(n0 + mm) * ldb + k0 + kk);
            Bs[kk + 0][mm] = bv.x; Bs[kk + 1][mm] = bv.y;
            Bs[kk + 2][mm] = bv.z; Bs[kk + 3][mm] = bv.w;
        }
        __syncthreads();
#pragma unroll
        for (int kk = 0; kk < 16; kk++) {
            float a[8], bb[8];
            *(float4*)&a[0]  = *(const float4*)&As[kk][trow * 8];
            *(float4*)&a[4]  = *(const float4*)&As[kk][trow * 8 + 4];
            *(float4*)&bb[0] = *(const float4*)&Bs[kk][tcol * 8];
            *(float4*)&bb[4] = *(const float4*)&Bs[kk][tcol * 8 + 4];
#pragma unroll
            for (int i = 0; i < 8; i++)
#pragma unroll
                for (int j = 0; j < 8; j++) acc[i][j] += a[i] * bb[j];
        }
        __syncthreads();
    }

    int rbase = m0 + trow * 8;
    int cbase = n0 + tcol * 8;
    if (mode == 0) {
#pragma unroll
        for (int i = 0; i < 8; i++) {
            int r = rbase + i;
            if (r < ROWS_PER_S) {
                int b = r & 15;
                const float* add = g_gictx + (size_t)(s * 16 + b) * G3 + cbase;
                float* dst = g_gi + (size_t)(s * ROWS_PER_S + r) * G3 + cbase;
#pragma unroll
                for (int j = 0; j < 8; j++) dst[j] = acc[i][j] + add[j];
            }
        }
    } else if (mode == 1) {
#pragma unroll
        for (int i = 0; i < 8; i++) {
            int r = rbase + i;
            if (r < 64) {
                float* dst = g_ctxlogit + (size_t)r * V_ + cbase;
#pragma unroll
                for (int j = 0; j < 8; j++) dst[j] = acc[i][j] + bias[cbase + j];
            }
        }
    } else {
#pragma unroll
        for (int i = 0; i < 8; i++) {
            int r = rbase + i;
            if (r < ROWS) {
                int s2 = r / ROWS_PER_S;
                int rr = r - s2 * ROWS_PER_S;
                int tt = rr >> 4;
                int b = rr & 15;
                float* dst = out + ((size_t)((b * S_ + s2) * L_ + tt + 1)) * V_ + cbase;
                const float* add = g_ctxlogit + (size_t)(s2 * 16 + b) * V_ + cbase;
#pragma unroll
                for (int j = 0; j < 8; j++) dst[j] = acc[i][j] + add[j];
            }
        }
    }
}

// ---------------------------------------------------------------------------
// One GRU step. grid (4 lines, 32 j-tiles of 16); 256 thr = 16 j x 16 b.
// Each thread computes gh_r/z/n for its (j,b), then h_new directly.
__global__ void __launch_bounds__(256) k_gru_step(
    int t, const float* __restrict__ W_hh, const float* __restrict__ b_hh) {
    int s = blockIdx.x;
    int jt = blockIdx.y;
    int tid = threadIdx.x;
    int b = tid & 15;
    int jl = tid >> 4;
    int j = jt * 16 + jl;

    __shared__ float h_sm[16][516];   // padded (2-way max conflict on .128)
    const float* hin = g_h[t & 1] + (size_t)s * B_ * H_;
    for (int i = tid; i < B_ * H_; i += 256)
        h_sm[i >> 9][i & 511] = hin[i];
    __syncthreads();

    const float4* wr4 = (const float4*)(W_hh + ((size_t)(s * G3) + j) * 512);
    const float4* wz4 = (const float4*)(W_hh + ((size_t)(s * G3) + 512 + j) * 512);
    const float4* wn4 = (const float4*)(W_hh + ((size_t)(s * G3) + 1024 + j) * 512);
    const float4* h4 = (const float4*)&h_sm[b][0];

    float rx = 0, ry = 0, rz = 0, rw = 0;
    float zx = 0, zy = 0, zz = 0, zw = 0;
    float nx = 0, ny = 0, nz = 0, nw = 0;
#pragma unroll 8
    for (int d = 0; d < 128; d++) {
        float4 h = h4[d];
        float4 a = wr4[d];
        float4 c = wz4[d];
        float4 e = wn4[d];
        rx += h.x * a.x; ry += h.y * a.y; rz += h.z * a.z; rw += h.w * a.w;
        zx += h.x * c.x; zy += h.y * c.y; zz += h.z * c.z; zw += h.w * c.w;
        nx += h.x * e.x; ny += h.y * e.y; nz += h.z * e.z; nw += h.w * e.w;
    }
    float ghr = (rx + ry) + (rz + rw) + b_hh[s * G3 + j];
    float ghz = (zx + zy) + (zz + zw) + b_hh[s * G3 + 512 + j];
    float ghn = (nx + ny) + (nz + nw) + b_hh[s * G3 + 1024 + j];

    int row = s * ROWS_PER_S + t * 16 + b;
    const float* gi = g_gi + (size_t)row * G3;
    float r = sigmoidf_(gi[j] + ghr);
    float z = sigmoidf_(gi[512 + j] + ghz);
    float n = tanhf(gi[1024 + j] + r * ghn);
    float hold = h_sm[b][j];
    float hnew = (1.0f - z) * n + z * hold;

    g_h[(t + 1) & 1][((size_t)s * 16 + b) * 512 + j] = hnew;
    g_A[(size_t)row * 1024 + 512 + j] = hnew;
}

// ---------------------------------------------------------------------------
extern "C" void kernel_launch(void* const* d_in, const int* in_sizes, int n_in,
                              void* d_out, int out_size) {
    const int*   input  = (const int*)d_in[0];
    const float* hidden = (const float*)d_in[1];
    const float* agg    = (const float*)d_in[2];
    const float* emb    = (const float*)d_in[3];
    const float* W_ih   = (const float*)d_in[4];
    const float* W_hh   = (const float*)d_in[5];
    const float* b_ih   = (const float*)d_in[6];
    const float* b_hh   = (const float*)d_in[7];
    const float* fc_W   = (const float*)d_in[8];
    const float* fc_b   = (const float*)d_in[9];
    float* out = (float*)d_out;

    // l=0 one-hot slices (also covers the 0xAA poison there)
    k_onehot<<<(64 * V_ + 255) / 256, 256>>>(out);
    // init h double-buffer
    k_hinit<<<(S_ * B_ * H_ + 255) / 256, 256>>>(hidden);
    // embedding gather into feats rows
    k_gather<<<ROWS, 128>>>(input, emb);
    // ctx part of gi (+bias)
    k_ctx_gi<<<(S_ * G3) / 8, 256>>>(hidden, agg, W_ih, b_ih);
    // emb part of gi (GEMM per line) -> g_gi
    k_gemm<<<dim3(12, 3, 4), 256>>>(0, nullptr, W_ih, nullptr, nullptr);
    // sequential GRU scan
    for (int t = 0; t < T_; t++)
        k_gru_step<<<dim3(4, 32), 256>>>(t, W_hh, b_hh);
    // agg @ fc_W[:,1024:] + fc_b -> ctx_logit
    k_gemm<<<dim3(V_ / 128, 1, 1), 256>>>(1, agg, fc_W + 1024, fc_b, nullptr);
    // main FC: [emb|h] @ fc_W[:,:1024] + ctx_logit -> scattered output
    k_gemm<<<dim3(V_ / 128, 12, 1), 256>>>(2, nullptr, fc_W, nullptr, out);
}

// round 3
// speedup vs baseline: 2.1280x; 2.1280x over previous
#include <cuda_runtime.h>
#include <cuda_bf16.h>
#include <math.h>
#include <stdint.h>

// Problem dims
#define S_ 4
#define B_ 16
#define T_ 23        // L-1
#define L_ 24
#define H_ 512
#define E_ 512
#define G3 1536      // 3H
#define V_ 32000
#define ROWS 1472    // S*T*B
#define ROWS_PER_S 368
#define MPAD 1536    // padded rows for tensor GEMM

// Scratch (device globals; no runtime allocation allowed)
__device__ float g_A[ROWS * 1024];        // per-row feats: [0:512)=emb, [512:1024)=h
__device__ float g_gi[ROWS * G3];         // gi_seq
__device__ float g_gictx[64 * G3];        // ctx part of gi (+ b_ih)
__device__ float g_h[2][S_ * B_ * H_];    // double-buffered hidden state
__device__ float g_ctxlogit[64 * V_];     // agg @ fc_W[:,1024:] + fc_b
__device__ __nv_bfloat16 g_Whi[(size_t)V_ * 1024];  // fc_W[:, :1024] hi
__device__ __nv_bfloat16 g_Wlo[(size_t)V_ * 1024];  // fc_W[:, :1024] lo
__device__ __nv_bfloat16 g_Ahi[(size_t)MPAD * 1024];
__device__ __nv_bfloat16 g_Alo[(size_t)MPAD * 1024];

static __device__ __forceinline__ float sigmoidf_(float x) {
    return 1.0f / (1.0f + expf(-x));
}

__device__ __forceinline__ uint32_t smem_u32(const void* p) {
    uint32_t a;
    asm("{ .reg .u64 t; cvta.to.shared.u64 t, %1; cvt.u32.u64 %0, t; }" : "=r"(a) : "l"(p));
    return a;
}

#define CP_ASYNC16(dst, src) \
    asm volatile("cp.async.cg.shared.global [%0], [%1], 16;" :: "r"(dst), "l"(src) : "memory")
#define CP_COMMIT() asm volatile("cp.async.commit_group;" ::: "memory")

#define LDSM4(r0, r1, r2, r3, addr) \
    asm volatile("ldmatrix.sync.aligned.m8n8.x4.shared.b16 {%0,%1,%2,%3}, [%4];" \
                 : "=r"(r0), "=r"(r1), "=r"(r2), "=r"(r3) : "r"(addr))

#define MMA16816(d, a, b0, b1) \
    asm volatile("mma.sync.aligned.m16n8k16.row.col.f32.bf16.bf16.f32 " \
                 "{%0,%1,%2,%3}, {%4,%5,%6,%7}, {%8,%9}, {%0,%1,%2,%3};" \
                 : "+f"((d)[0]), "+f"((d)[1]), "+f"((d)[2]), "+f"((d)[3]) \
                 : "r"((a)[0]), "r"((a)[1]), "r"((a)[2]), "r"((a)[3]), \
                   "r"(b0), "r"(b1))

// ===================== small kernels =====================
__global__ void k_onehot(float* __restrict__ out) {
    long i = (long)blockIdx.x * blockDim.x + threadIdx.x;
    if (i < (long)64 * V_) {
        int p = (int)(i / V_);
        int v = (int)(i - (long)p * V_);
        out[(size_t)p * L_ * V_ + v] = (v == 1) ? 1.0f : 0.0f;
    }
}

__global__ void k_hinit(const float* __restrict__ hidden) {
    int i = blockIdx.x * 256 + threadIdx.x;
    if (i < S_ * B_ * H_) g_h[0][i] = hidden[i];
}

__global__ void k_gather(const int* __restrict__ input, const float* __restrict__ emb) {
    int row = blockIdx.x;
    int s = row / ROWS_PER_S;
    int rr = row - s * ROWS_PER_S;
    int t = rr >> 4;
    int b = rr & 15;
    int tok = input[(b * S_ + s) * L_ + t];
    const float4* src = (const float4*)(emb + (size_t)tok * E_);
    float4* dst = (float4*)(g_A + (size_t)row * 1024);
    dst[threadIdx.x] = src[threadIdx.x];
}

// split fc_W[:, :1024] -> bf16 hi/lo
__global__ void k_wsplit(const float* __restrict__ fc_W) {
    long idx = (long)blockIdx.x * 256 + threadIdx.x;   // one float4 each
    if (idx >= (long)V_ * 256) return;
    int row = (int)(idx >> 8);
    int c4 = (int)(idx & 255);
    float4 v = *(const float4*)(fc_W + (size_t)row * G3 + c4 * 4);
    float xs[4] = {v.x, v.y, v.z, v.w};
    __nv_bfloat16 h0 = __float2bfloat16(xs[0]);
    __nv_bfloat16 h1 = __float2bfloat16(xs[1]);
    __nv_bfloat16 h2 = __float2bfloat16(xs[2]);
    __nv_bfloat16 h3 = __float2bfloat16(xs[3]);
    __nv_bfloat16 l0 = __float2bfloat16(xs[0] - __bfloat162float(h0));
    __nv_bfloat16 l1 = __float2bfloat16(xs[1] - __bfloat162float(h1));
    __nv_bfloat16 l2 = __float2bfloat16(xs[2] - __bfloat162float(h2));
    __nv_bfloat16 l3 = __float2bfloat16(xs[3] - __bfloat162float(h3));
    uint32_t hi01 = (uint32_t)__bfloat16_as_ushort(h0) | ((uint32_t)__bfloat16_as_ushort(h1) << 16);
    uint32_t hi23 = (uint32_t)__bfloat16_as_ushort(h2) | ((uint32_t)__bfloat16_as_ushort(h3) << 16);
    uint32_t lo01 = (uint32_t)__bfloat16_as_ushort(l0) | ((uint32_t)__bfloat16_as_ushort(l1) << 16);
    uint32_t lo23 = (uint32_t)__bfloat16_as_ushort(l2) | ((uint32_t)__bfloat16_as_ushort(l3) << 16);
    *(uint2*)(g_Whi + (size_t)row * 1024 + c4 * 4) = make_uint2(hi01, hi23);
    *(uint2*)(g_Wlo + (size_t)row * 1024 + c4 * 4) = make_uint2(lo01, lo23);
}

// split feats (g_A) -> bf16 hi/lo, zero-pad rows >= ROWS
__global__ void k_asplit() {
    int row = blockIdx.x;
    int c = threadIdx.x * 4;
    float4 v = make_float4(0.f, 0.f, 0.f, 0.f);
    if (row < ROWS) v = *(const float4*)(g_A + (size_t)row * 1024 + c);
    float xs[4] = {v.x, v.y, v.z, v.w};
    __nv_bfloat16 h0 = __float2bfloat16(xs[0]);
    __nv_bfloat16 h1 = __float2bfloat16(xs[1]);
    __nv_bfloat16 h2 = __float2bfloat16(xs[2]);
    __nv_bfloat16 h3 = __float2bfloat16(xs[3]);
    __nv_bfloat16 l0 = __float2bfloat16(xs[0] - __bfloat162float(h0));
    __nv_bfloat16 l1 = __float2bfloat16(xs[1] - __bfloat162float(h1));
    __nv_bfloat16 l2 = __float2bfloat16(xs[2] - __bfloat162float(h2));
    __nv_bfloat16 l3 = __float2bfloat16(xs[3] - __bfloat162float(h3));
    uint32_t hi01 = (uint32_t)__bfloat16_as_ushort(h0) | ((uint32_t)__bfloat16_as_ushort(h1) << 16);
    uint32_t hi23 = (uint32_t)__bfloat16_as_ushort(h2) | ((uint32_t)__bfloat16_as_ushort(h3) << 16);
    uint32_t lo01 = (uint32_t)__bfloat16_as_ushort(l0) | ((uint32_t)__bfloat16_as_ushort(l1) << 16);
    uint32_t lo23 = (uint32_t)__bfloat16_as_ushort(l2) | ((uint32_t)__bfloat16_as_ushort(l3) << 16);
    *(uint2*)(g_Ahi + (size_t)row * 1024 + c) = make_uint2(hi01, hi23);
    *(uint2*)(g_Alo + (size_t)row * 1024 + c) = make_uint2(lo01, lo23);
}

// gictx[s,b,g] = ctx[s,b,:] . W_ih[s,g,512:] + b_ih[s,g]
__global__ void k_ctx_gi(const float* __restrict__ hidden,
                         const float* __restrict__ agg,
                         const float* __restrict__ W_ih,
                         const float* __restrict__ b_ih) {
    int w = blockIdx.x * 8 + (threadIdx.x >> 5);
    int lane = threadIdx.x & 31;
    int s = w / G3;
    int g = w - s * G3;
    const float* ctx = (s == 0) ? agg : (hidden + (size_t)s * B_ * H_);
    const float* wrow = W_ih + ((size_t)(s * G3) + g) * 1024 + 512;
    float acc[16];
#pragma unroll
    for (int b = 0; b < 16; b++) acc[b] = 0.0f;
    for (int d = lane; d < 512; d += 32) {
        float wv = wrow[d];
#pragma unroll
        for (int b = 0; b < 16; b++) acc[b] += wv * ctx[b * 512 + d];
    }
    float res = 0.0f;
#pragma unroll
    for (int b = 0; b < 16; b++) {
        float v = acc[b];
#pragma unroll
        for (int off = 16; off; off >>= 1) v += __shfl_xor_sync(0xffffffffu, v, off);
        if (lane == b) res = v;
    }
    if (lane < 16)
        g_gictx[(size_t)(s * 16 + lane) * G3 + g] = res + b_ih[s * G3 + g];
}

// ===================== SIMT GEMM for small pieces (modes 0,1) =====================
__global__ void __launch_bounds__(256) k_gemm(
    int mode, const float* __restrict__ Aext, const float* __restrict__ Bext,
    const float* __restrict__ bias) {
    int s = blockIdx.z;
    const float* A;
    const float* B;
    int lda, ldb, M, K;
    if (mode == 0) {            // gi: emb part
        A = g_A + (size_t)s * ROWS_PER_S * 1024; lda = 1024;
        B = Bext + (size_t)s * G3 * 1024;        ldb = 1024;
        M = ROWS_PER_S; K = 512;
    } else {                    // ctx_logit
        A = Aext; lda = 512;
        B = Bext; ldb = 1536;
        M = 64; K = 512;
    }

    __shared__ float As[16][128];
    __shared__ float Bs[16][128];

    int tid = threadIdx.x;
    int m0 = blockIdx.y * 128;
    int n0 = blockIdx.x * 128;
    int trow = tid >> 4;
    int tcol = tid & 15;

    float acc[8][8];
#pragma unroll
    for (int i = 0; i < 8; i++)
#pragma unroll
        for (int j = 0; j < 8; j++) acc[i][j] = 0.0f;

    for (int k0 = 0; k0 < K; k0 += 16) {
#pragma unroll
        for (int it = 0; it < 2; it++) {
            int i = tid + it * 256;
            int mm = i >> 2;
            int kk = (i & 3) << 2;
            float4 av = make_float4(0.f, 0.f, 0.f, 0.f);
            if (m0 + mm < M)
                av = *(const float4*)(A + (size_t)(m0 + mm) * lda + k0 + kk);
            As[kk + 0][mm] = av.x; As[kk + 1][mm] = av.y;
            As[kk + 2][mm] = av.z; As[kk + 3][mm] = av.w;
            float4 bv = *(const float4*)(B + (size_t)(n0 + mm) * ldb + k0 + kk);
            Bs[kk + 0][mm] = bv.x; Bs[kk + 1][mm] = bv.y;
            Bs[kk + 2][mm] = bv.z; Bs[kk + 3][mm] = bv.w;
        }
        __syncthreads();
#pragma unroll
        for (int kk = 0; kk < 16; kk++) {
            float a[8], bb[8];
            *(float4*)&a[0]  = *(const float4*)&As[kk][trow * 8];
            *(float4*)&a[4]  = *(const float4*)&As[kk][trow * 8 + 4];
            *(float4*)&bb[0] = *(const float4*)&Bs[kk][tcol * 8];
            *(float4*)&bb[4] = *(const float4*)&Bs[kk][tcol * 8 + 4];
#pragma unroll
            for (int i = 0; i < 8; i++)
#pragma unroll
                for (int j = 0; j < 8; j++) acc[i][j] += a[i] * bb[j];
        }
        __syncthreads();
    }

    int rbase = m0 + trow * 8;
    int cbase = n0 + tcol * 8;
    if (mode == 0) {
#pragma unroll
        for (int i = 0; i < 8; i++) {
            int r = rbase + i;
            if (r < ROWS_PER_S) {
                int b = r & 15;
                const float* add = g_gictx + (size_t)(s * 16 + b) * G3 + cbase;
                float* dst = g_gi + (size_t)(s * ROWS_PER_S + r) * G3 + cbase;
#pragma unroll
                for (int j = 0; j < 8; j++) dst[j] = acc[i][j] + add[j];
            }
        }
    } else {
#pragma unroll
        for (int i = 0; i < 8; i++) {
            int r = rbase + i;
            if (r < 64) {
                float* dst = g_ctxlogit + (size_t)r * V_ + cbase;
#pragma unroll
                for (int j = 0; j < 8; j++) dst[j] = acc[i][j] + bias[cbase + j];
            }
        }
    }
}

// ===================== GRU step =====================
__global__ void __launch_bounds__(256) k_gru_step(
    int t, const float* __restrict__ W_hh, const float* __restrict__ b_hh) {
    int s = blockIdx.x;
    int jt = blockIdx.y;
    int tid = threadIdx.x;
    int b = tid & 15;
    int jl = tid >> 4;
    int j = jt * 16 + jl;

    __shared__ float h_sm[16][516];
    const float* hin = g_h[t & 1] + (size_t)s * B_ * H_;
    for (int i = tid; i < B_ * H_; i += 256)
        h_sm[i >> 9][i & 511] = hin[i];
    __syncthreads();

    const float4* wr4 = (const float4*)(W_hh + ((size_t)(s * G3) + j) * 512);
    const float4* wz4 = (const float4*)(W_hh + ((size_t)(s * G3) + 512 + j) * 512);
    const float4* wn4 = (const float4*)(W_hh + ((size_t)(s * G3) + 1024 + j) * 512);
    const float4* h4 = (const float4*)&h_sm[b][0];

    float rx = 0, ry = 0, rz = 0, rw = 0;
    float zx = 0, zy = 0, zz = 0, zw = 0;
    float nx = 0, ny = 0, nz = 0, nw = 0;
#pragma unroll 8
    for (int d = 0; d < 128; d++) {
        float4 h = h4[d];
        float4 a = wr4[d];
        float4 c = wz4[d];
        float4 e = wn4[d];
        rx += h.x * a.x; ry += h.y * a.y; rz += h.z * a.z; rw += h.w * a.w;
        zx += h.x * c.x; zy += h.y * c.y; zz += h.z * c.z; zw += h.w * c.w;
        nx += h.x * e.x; ny += h.y * e.y; nz += h.z * e.z; nw += h.w * e.w;
    }
    float ghr = (rx + ry) + (rz + rw) + b_hh[s * G3 + j];
    float ghz = (zx + zy) + (zz + zw) + b_hh[s * G3 + 512 + j];
    float ghn = (nx + ny) + (nz + nw) + b_hh[s * G3 + 1024 + j];

    int row = s * ROWS_PER_S + t * 16 + b;
    const float* gi = g_gi + (size_t)row * G3;
    float r = sigmoidf_(gi[j] + ghr);
    float z = sigmoidf_(gi[512 + j] + ghz);
    float n = tanhf(gi[1024 + j] + r * ghn);
    float hold = h_sm[b][j];
    float hnew = (1.0f - z) * n + z * hold;

    g_h[(t + 1) & 1][((size_t)s * 16 + b) * 512 + j] = hnew;
    g_A[(size_t)row * 1024 + 512 + j] = hnew;
}

// ===================== mma.sync FC GEMM =====================
// out[R,32000] += feats[.,1024] @ fc_W[:, :1024]^T via bf16 hi/lo (3 passes)
#define BM 128
#define BN 128
#define BK 32
#define NCHUNK 96          // 3 passes x 32 chunks of K=32
#define STAGEB 16384       // A 8KB + B 8KB
#define FC_SMEM (4 * STAGEB)

__global__ void __launch_bounds__(256, 2) k_fc(float* __restrict__ out) {
    extern __shared__ __align__(128) char sm_raw[];
    const uint32_t smem_base = smem_u32(sm_raw);
    const int tid = threadIdx.x;
    const int lane = tid & 31;
    const int w = tid >> 5;
    const int wm = w >> 1;      // 0..3
    const int wn = w & 1;       // 0..1
    const int m0 = blockIdx.x * BM;
    const int n0 = blockIdx.y * BN;

    float acc[2][8][4];
#pragma unroll
    for (int mt = 0; mt < 2; mt++)
#pragma unroll
        for (int nt = 0; nt < 8; nt++)
#pragma unroll
            for (int k = 0; k < 4; k++) acc[mt][nt][k] = 0.0f;

    // stage loader: chunk c -> stage c%4
    auto load_stage = [&](int c) {
        int pass = c >> 5;
        int kk = (c & 31) << 5;
        const __nv_bfloat16* Ap = ((pass < 2) ? g_Ahi : g_Alo) + (size_t)m0 * 1024 + kk;
        const __nv_bfloat16* Bp = ((pass == 1) ? g_Wlo : g_Whi) + (size_t)n0 * 1024 + kk;
        uint32_t sa = smem_base + (c & 3) * STAGEB;
        uint32_t sb = sa + 8192;
#pragma unroll
        for (int it = 0; it < 2; it++) {
            int idx = tid + it * 256;
            int r = idx >> 2, g = idx & 3;
            uint32_t dst = sa + r * 64 + ((g ^ ((r >> 1) & 3)) << 4);
            CP_ASYNC16(dst, Ap + (size_t)r * 1024 + g * 8);
        }
#pragma unroll
        for (int it = 0; it < 2; it++) {
            int idx = tid + it * 256;
            int r = idx >> 2, g = idx & 3;
            uint32_t dst = sb + r * 64 + ((g ^ ((r >> 1) & 3)) << 4);
            CP_ASYNC16(dst, Bp + (size_t)r * 1024 + g * 8);
        }
    };

    load_stage(0); CP_COMMIT();
    load_stage(1); CP_COMMIT();
    load_stage(2); CP_COMMIT();

    const int arow = wm * 32 + (lane & 15);
    const int aseg = lane >> 4;
    const int brow = wn * 64 + (lane & 7) + ((lane >> 4) << 3);
    const int bseg = (lane >> 3) & 1;

    for (int c = 0; c < NCHUNK; c++) {
        if (c < NCHUNK - 2)
            asm volatile("cp.async.wait_group 2;" ::: "memory");
        else if (c == NCHUNK - 2)
            asm volatile("cp.async.wait_group 1;" ::: "memory");
        else
            asm volatile("cp.async.wait_group 0;" ::: "memory");
        __syncthreads();
        if (c + 3 < NCHUNK) { load_stage(c + 3); CP_COMMIT(); }

        uint32_t sa = smem_base + (c & 3) * STAGEB;
        uint32_t sb = sa + 8192;
#pragma unroll
        for (int ks = 0; ks < 2; ks++) {
            uint32_t ra[2][4], rb[4][4];
#pragma unroll
            for (int mt = 0; mt < 2; mt++) {
                int r = arow + mt * 16;
                int seg = 2 * ks + aseg;
                uint32_t addr = sa + r * 64 + ((seg ^ ((r >> 1) & 3)) << 4);
                LDSM4(ra[mt][0], ra[mt][1], ra[mt][2], ra[mt][3], addr);
            }
#pragma unroll
            for (int nt2 = 0; nt2 < 4; nt2++) {
                int r = brow + nt2 * 16;
                int seg = 2 * ks + bseg;
                uint32_t addr = sb + r * 64 + ((seg ^ ((r >> 1) & 3)) << 4);
                LDSM4(rb[nt2][0], rb[nt2][1], rb[nt2][2], rb[nt2][3], addr);
            }
#pragma unroll
            for (int mt = 0; mt < 2; mt++)
#pragma unroll
                for (int nt = 0; nt < 8; nt++)
                    MMA16816(acc[mt][nt], ra[mt],
                             rb[nt >> 1][(nt & 1) * 2], rb[nt >> 1][(nt & 1) * 2 + 1]);
        }
        __syncthreads();
    }

    // epilogue: scatter + ctxlogit add
#pragma unroll
    for (int mt = 0; mt < 2; mt++) {
#pragma unroll
        for (int half = 0; half < 2; half++) {
            int R = m0 + wm * 32 + mt * 16 + (lane >> 2) + half * 8;
            if (R >= ROWS) continue;
            int s2 = R / ROWS_PER_S;
            int rr = R - s2 * ROWS_PER_S;
            int tt = rr >> 4;
            int b = rr & 15;
            float* dst = out + ((size_t)((b * S_ + s2) * L_ + tt + 1)) * V_;
            const float* ctx = g_ctxlogit + (size_t)(s2 * 16 + b) * V_;
#pragma unroll
            for (int nt = 0; nt < 8; nt++) {
                int col = n0 + wn * 64 + nt * 8 + (lane & 3) * 2;
                float2 cv = *(const float2*)(ctx + col);
                float2 o;
                o.x = acc[mt][nt][half * 2 + 0] + cv.x;
                o.y = acc[mt][nt][half * 2 + 1] + cv.y;
                *(float2*)(dst + col) = o;
            }
        }
    }
}

// ===================== launch =====================
extern "C" void kernel_launch(void* const* d_in, const int* in_sizes, int n_in,
                              void* d_out, int out_size) {
    const int*   input  = (const int*)d_in[0];
    const float* hidden = (const float*)d_in[1];
    const float* agg    = (const float*)d_in[2];
    const float* emb    = (const float*)d_in[3];
    const float* W_ih   = (const float*)d_in[4];
    const float* W_hh   = (const float*)d_in[5];
    const float* b_ih   = (const float*)d_in[6];
    const float* b_hh   = (const float*)d_in[7];
    const float* fc_W   = (const float*)d_in[8];
    const float* fc_b   = (const float*)d_in[9];
    float* out = (float*)d_out;

    cudaFuncSetAttribute(k_fc, cudaFuncAttributeMaxDynamicSharedMemorySize, FC_SMEM);

    k_onehot<<<(64 * V_ + 255) / 256, 256>>>(out);
    k_hinit<<<(S_ * B_ * H_ + 255) / 256, 256>>>(hidden);
    k_gather<<<ROWS, 128>>>(input, emb);
    k_wsplit<<<(int)(((long)V_ * 256 + 255) / 256), 256>>>(fc_W);
    k_ctx_gi<<<(S_ * G3) / 8, 256>>>(hidden, agg, W_ih, b_ih);
    k_gemm<<<dim3(12, 3, 4), 256>>>(0, nullptr, W_ih, nullptr);
    for (int t = 0; t < T_; t++)
        k_gru_step<<<dim3(4, 32), 256>>>(t, W_hh, b_hh);
    k_asplit<<<MPAD, 256>>>();
    k_gemm<<<dim3(V_ / 128, 1, 1), 256>>>(1, agg, fc_W + 1024, fc_b);
    k_fc<<<dim3(MPAD / BM, V_ / BN), 256, FC_SMEM>>>(out);
}

// round 5
// speedup vs baseline: 2.4452x; 1.1491x over previous
#include <cuda_runtime.h>
#include <cuda_bf16.h>
#include <math.h>
#include <stdint.h>

// Problem dims
#define S_ 4
#define B_ 16
#define T_ 23        // L-1
#define L_ 24
#define H_ 512
#define E_ 512
#define G3 1536      // 3H
#define V_ 32000
#define ROWS 1472    // S*T*B
#define ROWS_PER_S 368
#define MPAD 1536    // padded rows for tensor GEMM

// Scratch (device globals; no runtime allocation allowed)
__device__ float g_A[ROWS * 1024];        // per-row feats fp32 (emb half used by gi GEMM)
__device__ float g_gi[ROWS * G3];         // gi_seq
__device__ float g_gictx[64 * G3];        // ctx part of gi (+ b_ih)
__device__ float g_h[2][S_ * B_ * H_];    // double-buffered hidden state
__device__ float g_ctxlogit[64 * V_];     // agg @ fc_W[:,1024:] + fc_b
__device__ __nv_bfloat16 g_Whi[(size_t)V_ * 1024];  // fc_W[:, :1024] hi
__device__ __nv_bfloat16 g_Wlo[(size_t)V_ * 1024];  // fc_W[:, :1024] lo
__device__ __nv_bfloat16 g_Ahi[(size_t)MPAD * 1024];  // rows >= ROWS stay zero (zero-init)
__device__ __nv_bfloat16 g_Alo[(size_t)MPAD * 1024];
__device__ unsigned g_bar;                // scan barrier counter (reset by k_wsplit)

static __device__ __forceinline__ float sigmoidf_(float x) {
    return 1.0f / (1.0f + expf(-x));
}

__device__ __forceinline__ uint32_t smem_u32(const void* p) {
    uint32_t a;
    asm("{ .reg .u64 t; cvta.to.shared.u64 t, %1; cvt.u32.u64 %0, t; }" : "=r"(a) : "l"(p));
    return a;
}

#define CP_ASYNC16(dst, src) \
    asm volatile("cp.async.cg.shared.global [%0], [%1], 16;" :: "r"(dst), "l"(src) : "memory")
#define CP_COMMIT() asm volatile("cp.async.commit_group;" ::: "memory")

#define LDSM4(r0, r1, r2, r3, addr) \
    asm volatile("ldmatrix.sync.aligned.m8n8.x4.shared.b16 {%0,%1,%2,%3}, [%4];" \
                 : "=r"(r0), "=r"(r1), "=r"(r2), "=r"(r3) : "r"(addr))

#define MMA16816(d, a, b0, b1) \
    asm volatile("mma.sync.aligned.m16n8k16.row.col.f32.bf16.bf16.f32 " \
                 "{%0,%1,%2,%3}, {%4,%5,%6,%7}, {%8,%9}, {%0,%1,%2,%3};" \
                 : "+f"((d)[0]), "+f"((d)[1]), "+f"((d)[2]), "+f"((d)[3]) \
                 : "r"((a)[0]), "r"((a)[1]), "r"((a)[2]), "r"((a)[3]), \
                   "r"(b0), "r"(b1))

__device__ __forceinline__ void bf16_split4(float4 v, uint2& hi, uint2& lo) {
    __nv_bfloat16 h0 = __float2bfloat16(v.x);
    __nv_bfloat16 h1 = __float2bfloat16(v.y);
    __nv_bfloat16 h2 = __float2bfloat16(v.z);
    __nv_bfloat16 h3 = __float2bfloat16(v.w);
    __nv_bfloat16 l0 = __float2bfloat16(v.x - __bfloat162float(h0));
    __nv_bfloat16 l1 = __float2bfloat16(v.y - __bfloat162float(h1));
    __nv_bfloat16 l2 = __float2bfloat16(v.z - __bfloat162float(h2));
    __nv_bfloat16 l3 = __float2bfloat16(v.w - __bfloat162float(h3));
    hi.x = (uint32_t)__bfloat16_as_ushort(h0) | ((uint32_t)__bfloat16_as_ushort(h1) << 16);
    hi.y = (uint32_t)__bfloat16_as_ushort(h2) | ((uint32_t)__bfloat16_as_ushort(h3) << 16);
    lo.x = (uint32_t)__bfloat16_as_ushort(l0) | ((uint32_t)__bfloat16_as_ushort(l1) << 16);
    lo.y = (uint32_t)__bfloat16_as_ushort(l2) | ((uint32_t)__bfloat16_as_ushort(l3) << 16);
}

// ===================== small kernels =====================
__global__ void k_onehot(float* __restrict__ out) {
    long i = (long)blockIdx.x * blockDim.x + threadIdx.x;
    if (i < (long)64 * V_) {
        int p = (int)(i / V_);
        int v = (int)(i - (long)p * V_);
        out[(size_t)p * L_ * V_ + v] = (v == 1) ? 1.0f : 0.0f;
    }
}

// gather embeddings -> g_A fp32 (for gi GEMM) and g_Ahi/g_Alo bf16 (for FC)
__global__ void k_gather(const int* __restrict__ input, const float* __restrict__ emb) {
    int row = blockIdx.x;
    int s = row / ROWS_PER_S;
    int rr = row - s * ROWS_PER_S;
    int t = rr >> 4;
    int b = rr & 15;
    int tok = input[(b * S_ + s) * L_ + t];
    float4 v = ((const float4*)(emb + (size_t)tok * E_))[threadIdx.x];
    ((float4*)(g_A + (size_t)row * 1024))[threadIdx.x] = v;
    uint2 hi, lo;
    bf16_split4(v, hi, lo);
    *(uint2*)(g_Ahi + (size_t)row * 1024 + threadIdx.x * 4) = hi;
    *(uint2*)(g_Alo + (size_t)row * 1024 + threadIdx.x * 4) = lo;
}

// split fc_W[:, :1024] -> bf16 hi/lo ; also resets scan barrier
__global__ void k_wsplit(const float* __restrict__ fc_W) {
    long idx = (long)blockIdx.x * 256 + threadIdx.x;   // one float4 each
    if (idx == 0) g_bar = 0;
    if (idx >= (long)V_ * 256) return;
    int row = (int)(idx >> 8);
    int c4 = (int)(idx & 255);
    float4 v = *(const float4*)(fc_W + (size_t)row * G3 + c4 * 4);
    uint2 hi, lo;
    bf16_split4(v, hi, lo);
    *(uint2*)(g_Whi + (size_t)row * 1024 + c4 * 4) = hi;
    *(uint2*)(g_Wlo + (size_t)row * 1024 + c4 * 4) = lo;
}

// gictx[s,b,g] = ctx[s,b,:] . W_ih[s,g,512:] + b_ih[s,g]
__global__ void k_ctx_gi(const float* __restrict__ hidden,
                         const float* __restrict__ agg,
                         const float* __restrict__ W_ih,
                         const float* __restrict__ b_ih) {
    int w = blockIdx.x * 8 + (threadIdx.x >> 5);
    int lane = threadIdx.x & 31;
    int s = w / G3;
    int g = w - s * G3;
    const float* ctx = (s == 0) ? agg : (hidden + (size_t)s * B_ * H_);
    const float* wrow = W_ih + ((size_t)(s * G3) + g) * 1024 + 512;
    float acc[16];
#pragma unroll
    for (int b = 0; b < 16; b++) acc[b] = 0.0f;
    for (int d = lane; d < 512; d += 32) {
        float wv = wrow[d];
#pragma unroll
        for (int b = 0; b < 16; b++) acc[b] += wv * ctx[b * 512 + d];
    }
    float res = 0.0f;
#pragma unroll
    for (int b = 0; b < 16; b++) {
        float v = acc[b];
#pragma unroll
        for (int off = 16; off; off >>= 1) v += __shfl_xor_sync(0xffffffffu, v, off);
        if (lane == b) res = v;
    }
    if (lane < 16)
        g_gictx[(size_t)(s * 16 + lane) * G3 + g] = res + b_ih[s * G3 + g];
}

// ===================== SIMT GEMM for small pieces (modes 0,1) =====================
__global__ void __launch_bounds__(256) k_gemm(
    int mode, const float* __restrict__ Aext, const float* __restrict__ Bext,
    const float* __restrict__ bias) {
    int s = blockIdx.z;
    const float* A;
    const float* B;
    int lda, ldb, M, K;
    if (mode == 0) {            // gi: emb part
        A = g_A + (size_t)s * ROWS_PER_S * 1024; lda = 1024;
        B = Bext + (size_t)s * G3 * 1024;        ldb = 1024;
        M = ROWS_PER_S; K = 512;
    } else {                    // ctx_logit
        A = Aext; lda = 512;
        B = Bext; ldb = 1536;
        M = 64; K = 512;
    }

    __shared__ float As[16][128];
    __shared__ float Bs[16][128];

    int tid = threadIdx.x;
    int m0 = blockIdx.y * 128;
    int n0 = blockIdx.x * 128;
    int trow = tid >> 4;
    int tcol = tid & 15;

    float acc[8][8];
#pragma unroll
    for (int i = 0; i < 8; i++)
#pragma unroll
        for (int j = 0; j < 8; j++) acc[i][j] = 0.0f;

    for (int k0 = 0; k0 < K; k0 += 16) {
#pragma unroll
        for (int it = 0; it < 2; it++) {
            int i = tid + it * 256;
            int mm = i >> 2;
            int kk = (i & 3) << 2;
            float4 av = make_float4(0.f, 0.f, 0.f, 0.f);
            if (m0 + mm < M)
                av = *(const float4*)(A + (size_t)(m0 + mm) * lda + k0 + kk);
            As[kk + 0][mm] = av.x; As[kk + 1][mm] = av.y;
            As[kk + 2][mm] = av.z; As[kk + 3][mm] = av.w;
            float4 bv = *(const float4*)(B + (size_t)(n0 + mm) * ldb + k0 + kk);
            Bs[kk + 0][mm] = bv.x; Bs[kk + 1][mm] = bv.y;
            Bs[kk + 2][mm] = bv.z; Bs[kk + 3][mm] = bv.w;
        }
        __syncthreads();
#pragma unroll
        for (int kk = 0; kk < 16; kk++) {
            float a[8], bb[8];
            *(float4*)&a[0]  = *(const float4*)&As[kk][trow * 8];
            *(float4*)&a[4]  = *(const float4*)&As[kk][trow * 8 + 4];
            *(float4*)&bb[0] = *(const float4*)&Bs[kk][tcol * 8];
            *(float4*)&bb[4] = *(const float4*)&Bs[kk][tcol * 8 + 4];
#pragma unroll
            for (int i = 0; i < 8; i++)
#pragma unroll
                for (int j = 0; j < 8; j++) acc[i][j] += a[i] * bb[j];
        }
        __syncthreads();
    }

    int rbase = m0 + trow * 8;
    int cbase = n0 + tcol * 8;
    if (mode == 0) {
#pragma unroll
        for (int i = 0; i < 8; i++) {
            int r = rbase + i;
            if (r < ROWS_PER_S) {
                int b = r & 15;
                const float* add = g_gictx + (size_t)(s * 16 + b) * G3 + cbase;
                float* dst = g_gi + (size_t)(s * ROWS_PER_S + r) * G3 + cbase;
#pragma unroll
                for (int j = 0; j < 8; j++) dst[j] = acc[i][j] + add[j];
            }
        }
    } else {
#pragma unroll
        for (int i = 0; i < 8; i++) {
            int r = rbase + i;
            if (r < 64) {
                float* dst = g_ctxlogit + (size_t)r * V_ + cbase;
#pragma unroll
                for (int j = 0; j < 8; j++) dst[j] = acc[i][j] + bias[cbase + j];
            }
        }
    }
}

// ===================== persistent GRU scan =====================
// 128 CTAs (s x 32 j-tiles), all resident; global barrier per step.
#define WPAD 1544
#define SCAN_SMEM ((16 * WPAD + 16 * 516) * 4)

__global__ void __launch_bounds__(256) k_gru_scan(
    const float* __restrict__ hidden, const float* __restrict__ W_hh,
    const float* __restrict__ b_hh) {
    extern __shared__ float sm[];
    float* Wsm = sm;                 // [16][WPAD]
    float* hsm = sm + 16 * WPAD;     // [16][516]
    int bid = blockIdx.x;
    int s = bid >> 5, jt = bid & 31;
    int tid = threadIdx.x;
    int b = tid & 15, jl = tid >> 4;
    int j = jt * 16 + jl;

    // load 16 j's x 3 gates x 512 W values into smem (once)
    for (int i = tid; i < 16 * 3 * 128; i += 256) {
        int jj = i / 384;
        int rem = i - jj * 384;
        int gate = rem >> 7;
        int d4 = rem & 127;
        float4 v = *(const float4*)(W_hh +
            ((size_t)(s * G3 + gate * 512 + jt * 16 + jj)) * 512 + d4 * 4);
        *(float4*)(Wsm + jj * WPAD + gate * 512 + d4 * 4) = v;
    }
    float bhr = b_hh[s * G3 + j];
    float bhz = b_hh[s * G3 + 512 + j];
    float bhn = b_hh[s * G3 + 1024 + j];
    __syncthreads();

    const float4* wr = (const float4*)(Wsm + jl * WPAD);
    const float4* wz = (const float4*)(Wsm + jl * WPAD + 512);
    const float4* wn = (const float4*)(Wsm + jl * WPAD + 1024);

    for (int t = 0; t < T_; t++) {
        const float* hin = (t == 0) ? (hidden + (size_t)s * B_ * H_)
                                    : (g_h[t & 1] + (size_t)s * B_ * H_);
        for (int i = tid; i < B_ * H_; i += 256)
            hsm[(i >> 9) * 516 + (i & 511)] = hin[i];
        __syncthreads();

        const float4* h4 = (const float4*)(hsm + b * 516);
        float rx = 0, ry = 0, rz = 0, rw = 0;
        float zx = 0, zy = 0, zz = 0, zw = 0;
        float nx = 0, ny = 0, nz = 0, nw = 0;
#pragma unroll 8
        for (int d = 0; d < 128; d++) {
            float4 h = h4[d];
            float4 a = wr[d];
            float4 c = wz[d];
            float4 e = wn[d];
            rx += h.x * a.x; ry += h.y * a.y; rz += h.z * a.z; rw += h.w * a.w;
            zx += h.x * c.x; zy += h.y * c.y; zz += h.z * c.z; zw += h.w * c.w;
            nx += h.x * e.x; ny += h.y * e.y; nz += h.z * e.z; nw += h.w * e.w;
        }
        float ghr = (rx + ry) + (rz + rw) + bhr;
        float ghz = (zx + zy) + (zz + zw) + bhz;
        float ghn = (nx + ny) + (nz + nw) + bhn;

        int row = s * ROWS_PER_S + t * 16 + b;
        const float* gi = g_gi + (size_t)row * G3;
        float r = sigmoidf_(gi[j] + ghr);
        float z = sigmoidf_(gi[512 + j] + ghz);
        float n = tanhf(gi[1024 + j] + r * ghn);
        float hold = hsm[b * 516 + j];
        float hnew = (1.0f - z) * n + z * hold;

        g_h[(t + 1) & 1][((size_t)s * 16 + b) * 512 + j] = hnew;
        __nv_bfloat16 hh = __float2bfloat16(hnew);
        __nv_bfloat16 hl = __float2bfloat16(hnew - __bfloat162float(hh));
        g_Ahi[(size_t)row * 1024 + 512 + j] = hh;
        g_Alo[(size_t)row * 1024 + 512 + j] = hl;

        __threadfence();
        __syncthreads();          // all threads done writing + hsm reads done
        if (tid == 0) {
            atomicAdd(&g_bar, 1u);
            unsigned target = 128u * (unsigned)(t + 1);
            while (*((volatile unsigned*)&g_bar) < target) { }
        }
        __syncthreads();
        __threadfence();
    }
}

// ===================== mma.sync FC GEMM v2 (pass-fused, 64x64 warp tiles) =====
// out[R,32000] = feats_bf16hi/lo[.,1024] @ W_bf16hi/lo^T (3 products) + ctxlogit
#define BM 128
#define BN 128
#define NCHUNK 32              // K=1024 / 32
#define STAGEB 32768           // Ahi 8K | Alo 8K | Bhi 8K | Blo 8K
#define FC_SMEM (3 * STAGEB)

__global__ void __launch_bounds__(128, 2) k_fc(float* __restrict__ out) {
    extern __shared__ __align__(128) char sm_raw[];
    const uint32_t smem_base = smem_u32(sm_raw);
    const int tid = threadIdx.x;
    const int lane = tid & 31;
    const int w = tid >> 5;
    const int wm = w >> 1;      // 0..1
    const int wn = w & 1;       // 0..1
    const int m0 = blockIdx.x * BM;
    const int n0 = blockIdx.y * BN;

    float acc[4][8][4];
#pragma unroll
    for (int mt = 0; mt < 4; mt++)
#pragma unroll
        for (int nt = 0; nt < 8; nt++)
#pragma unroll
            for (int k = 0; k < 4; k++) acc[mt][nt][k] = 0.0f;

    auto load_stage = [&](int c) {
        int kk = c << 5;
        uint32_t st = smem_base + (c % 3) * STAGEB;
        const __nv_bfloat16* Ah = g_Ahi + (size_t)m0 * 1024 + kk;
        const __nv_bfloat16* Al = g_Alo + (size_t)m0 * 1024 + kk;
        const __nv_bfloat16* Bh = g_Whi + (size_t)n0 * 1024 + kk;
        const __nv_bfloat16* Bl = g_Wlo + (size_t)n0 * 1024 + kk;
#pragma unroll
        for (int it = 0; it < 4; it++) {
            int idx = tid + it * 128;
            int r = idx >> 2, g = idx & 3;
            uint32_t doff = r * 64 + ((g ^ ((r >> 1) & 3)) << 4);
            size_t soff = (size_t)r * 1024 + g * 8;
            CP_ASYNC16(st + doff, Ah + soff);
            CP_ASYNC16(st + 8192 + doff, Al + soff);
            CP_ASYNC16(st + 16384 + doff, Bh + soff);
            CP_ASYNC16(st + 24576 + doff, Bl + soff);
        }
    };

    load_stage(0); CP_COMMIT();
    load_stage(1); CP_COMMIT();

    const int arow_b = wm * 64 + (lane & 15);
    const int aseg_b = lane >> 4;
    const int brow_b = wn * 64 + (lane & 7) + ((lane >> 4) << 3);
    const int bseg_b = (lane >> 3) & 1;

    for (int c = 0; c < NCHUNK; c++) {
        if (c + 1 < NCHUNK)
            asm volatile("cp.async.wait_group 1;" ::: "memory");
        else
            asm volatile("cp.async.wait_group 0;" ::: "memory");
        __syncthreads();
        if (c + 2 < NCHUNK) { load_stage(c + 2); CP_COMMIT(); }

        uint32_t sa = smem_base + (c % 3) * STAGEB;
        uint32_t sbh = sa + 16384;
#pragma unroll
        for (int ks = 0; ks < 2; ks++) {
            uint32_t ra_h[4][4], ra_l[4][4];
#pragma unroll
            for (int mt = 0; mt < 4; mt++) {
                int r = arow_b + mt * 16;
                int seg = 2 * ks + aseg_b;
                uint32_t doff = r * 64 + ((seg ^ ((r >> 1) & 3)) << 4);
                LDSM4(ra_h[mt][0], ra_h[mt][1], ra_h[mt][2], ra_h[mt][3], sa + doff);
                LDSM4(ra_l[mt][0], ra_l[mt][1], ra_l[mt][2], ra_l[mt][3], sa + 8192 + doff);
            }
#pragma unroll
            for (int nt2 = 0; nt2 < 4; nt2++) {
                int r = brow_b + nt2 * 16;
                int seg = 2 * ks + bseg_b;
                uint32_t doff = r * 64 + ((seg ^ ((r >> 1) & 3)) << 4);
                uint32_t rb_h[4], rb_l[4];
                LDSM4(rb_h[0], rb_h[1], rb_h[2], rb_h[3], sbh + doff);
                LDSM4(rb_l[0], rb_l[1], rb_l[2], rb_l[3], sbh + 8192 + doff);
                // pass 0: hi*hi
#pragma unroll
                for (int mt = 0; mt < 4; mt++) {
                    MMA16816(acc[mt][nt2 * 2 + 0], ra_h[mt], rb_h[0], rb_h[1]);
                    MMA16816(acc[mt][nt2 * 2 + 1], ra_h[mt], rb_h[2], rb_h[3]);
                }
                // pass 1: hi*lo
#pragma unroll
                for (int mt = 0; mt < 4; mt++) {
                    MMA16816(acc[mt][nt2 * 2 + 0], ra_h[mt], rb_l[0], rb_l[1]);
                    MMA16816(acc[mt][nt2 * 2 + 1], ra_h[mt], rb_l[2], rb_l[3]);
                }
                // pass 2: lo*hi
#pragma unroll
                for (int mt = 0; mt < 4; mt++) {
                    MMA16816(acc[mt][nt2 * 2 + 0], ra_l[mt], rb_h[0], rb_h[1]);
                    MMA16816(acc[mt][nt2 * 2 + 1], ra_l[mt], rb_h[2], rb_h[3]);
                }
            }
        }
        __syncthreads();
    }

    // epilogue: scatter + ctxlogit add
#pragma unroll
    for (int mt = 0; mt < 4; mt++) {
#pragma unroll
        for (int half = 0; half < 2; half++) {
            int R = m0 + wm * 64 + mt * 16 + (lane >> 2) + half * 8;
            if (R >= ROWS) continue;
            int s2 = R / ROWS_PER_S;
            int rr = R - s2 * ROWS_PER_S;
            int tt = rr >> 4;
            int b = rr & 15;
            float* dst = out + ((size_t)((b * S_ + s2) * L_ + tt + 1)) * V_;
            const float* ctx = g_ctxlogit + (size_t)(s2 * 16 + b) * V_;
#pragma unroll
            for (int nt = 0; nt < 8; nt++) {
                int col = n0 + wn * 64 + nt * 8 + (lane & 3) * 2;
                float2 cv = *(const float2*)(ctx + col);
                float2 o;
                o.x = acc[mt][nt][half * 2 + 0] + cv.x;
                o.y = acc[mt][nt][half * 2 + 1] + cv.y;
                *(float2*)(dst + col) = o;
            }
        }
    }
}

// ===================== launch =====================
extern "C" void kernel_launch(void* const* d_in, const int* in_sizes, int n_in,
                              void* d_out, int out_size) {
    const int*   input  = (const int*)d_in[0];
    const float* hidden = (const float*)d_in[1];
    const float* agg    = (const float*)d_in[2];
    const float* emb    = (const float*)d_in[3];
    const float* W_ih   = (const float*)d_in[4];
    const float* W_hh   = (const float*)d_in[5];
    const float* b_ih   = (const float*)d_in[6];
    const float* b_hh   = (const float*)d_in[7];
    const float* fc_W   = (const float*)d_in[8];
    const float* fc_b   = (const float*)d_in[9];
    float* out = (float*)d_out;

    cudaFuncSetAttribute(k_fc, cudaFuncAttributeMaxDynamicSharedMemorySize, FC_SMEM);
    cudaFuncSetAttribute(k_gru_scan, cudaFuncAttributeMaxDynamicSharedMemorySize, SCAN_SMEM);

    k_onehot<<<(64 * V_ + 255) / 256, 256>>>(out);
    k_gather<<<ROWS, 128>>>(input, emb);
    k_wsplit<<<(int)(((long)V_ * 256 + 255) / 256), 256>>>(fc_W);
    k_ctx_gi<<<(S_ * G3) / 8, 256>>>(hidden, agg, W_ih, b_ih);
    k_gemm<<<dim3(12, 3, 4), 256>>>(0, nullptr, W_ih, nullptr);
    k_gru_scan<<<128, 256, SCAN_SMEM>>>(hidden, W_hh, b_hh);
    k_gemm<<<dim3(V_ / 128, 1, 1), 256>>>(1, agg, fc_W + 1024, fc_b);
    k_fc<<<dim3(MPAD / BM, V_ / BN), 128, FC_SMEM>>>(out);
}

// round 6
// speedup vs baseline: 3.1115x; 1.2725x over previous
#include <cuda_runtime.h>
#include <cuda_fp16.h>
#include <math.h>
#include <stdint.h>

// Problem dims
#define S_ 4
#define B_ 16
#define T_ 23        // L-1
#define L_ 24
#define H_ 512
#define E_ 512
#define G3 1536      // 3H
#define V_ 32000
#define ROWS 1472    // S*T*B
#define ROWS_PER_S 368
#define MPAD 1536    // padded rows for tensor GEMM

// Scratch (device globals; no runtime allocation allowed)
__device__ float g_A[ROWS * 1024];        // per-row feats fp32 (emb half used by gi GEMM)
__device__ float g_gi[ROWS * G3];         // gi_seq
__device__ float g_gictx[64 * G3];        // ctx part of gi (+ b_ih)
__device__ float g_h[2][S_ * B_ * H_];    // double-buffered hidden state
__device__ float g_ctxlogit[64 * V_];     // agg @ fc_W[:,1024:] + fc_b
__device__ __half g_Wh[(size_t)V_ * 1024];   // fc_W[:, :1024] fp16
__device__ __half g_Wc[(size_t)V_ * 512];    // fc_W[:, 1024:] fp16
__device__ __half g_Ahi[(size_t)MPAD * 1024]; // feats fp16 hi (pad rows stay zero)
__device__ __half g_Alo[(size_t)MPAD * 1024]; // feats fp16 lo
__device__ __half g_Chi[128 * 512];           // agg fp16 hi (rows 64.. stay zero)
__device__ __half g_Clo[128 * 512];           // agg fp16 lo
__device__ unsigned g_bar;                // scan barrier counter (reset by k_wsplit)

static __device__ __forceinline__ float sigmoidf_(float x) {
    return 1.0f / (1.0f + expf(-x));
}

__device__ __forceinline__ uint32_t smem_u32(const void* p) {
    uint32_t a;
    asm("{ .reg .u64 t; cvta.to.shared.u64 t, %1; cvt.u32.u64 %0, t; }" : "=r"(a) : "l"(p));
    return a;
}

#define CP_ASYNC16(dst, src) \
    asm volatile("cp.async.cg.shared.global [%0], [%1], 16;" :: "r"(dst), "l"(src) : "memory")
#define CP_COMMIT() asm volatile("cp.async.commit_group;" ::: "memory")

#define LDSM4(r0, r1, r2, r3, addr) \
    asm volatile("ldmatrix.sync.aligned.m8n8.x4.shared.b16 {%0,%1,%2,%3}, [%4];" \
                 : "=r"(r0), "=r"(r1), "=r"(r2), "=r"(r3) : "r"(addr))

#define MMA16816H(d, a, b0, b1) \
    asm volatile("mma.sync.aligned.m16n8k16.row.col.f32.f16.f16.f32 " \
                 "{%0,%1,%2,%3}, {%4,%5,%6,%7}, {%8,%9}, {%0,%1,%2,%3};" \
                 : "+f"((d)[0]), "+f"((d)[1]), "+f"((d)[2]), "+f"((d)[3]) \
                 : "r"((a)[0]), "r"((a)[1]), "r"((a)[2]), "r"((a)[3]), \
                   "r"(b0), "r"(b1))

// split float4 -> fp16 hi (8B) + fp16 lo (8B)
__device__ __forceinline__ void fp16_split4(float4 v, uint2& hi, uint2& lo) {
    __half h0 = __float2half(v.x), h1 = __float2half(v.y);
    __half h2 = __float2half(v.z), h3 = __float2half(v.w);
    __half l0 = __float2half(v.x - __half2float(h0));
    __half l1 = __float2half(v.y - __half2float(h1));
    __half l2 = __float2half(v.z - __half2float(h2));
    __half l3 = __float2half(v.w - __half2float(h3));
    hi.x = (uint32_t)__half_as_ushort(h0) | ((uint32_t)__half_as_ushort(h1) << 16);
    hi.y = (uint32_t)__half_as_ushort(h2) | ((uint32_t)__half_as_ushort(h3) << 16);
    lo.x = (uint32_t)__half_as_ushort(l0) | ((uint32_t)__half_as_ushort(l1) << 16);
    lo.y = (uint32_t)__half_as_ushort(l2) | ((uint32_t)__half_as_ushort(l3) << 16);
}
__device__ __forceinline__ uint2 fp16_pack4(float4 v) {
    __half h0 = __float2half(v.x), h1 = __float2half(v.y);
    __half h2 = __float2half(v.z), h3 = __float2half(v.w);
    uint2 r;
    r.x = (uint32_t)__half_as_ushort(h0) | ((uint32_t)__half_as_ushort(h1) << 16);
    r.y = (uint32_t)__half_as_ushort(h2) | ((uint32_t)__half_as_ushort(h3) << 16);
    return r;
}

// ===================== small kernels =====================
__global__ void k_onehot(float* __restrict__ out) {
    long i = (long)blockIdx.x * blockDim.x + threadIdx.x;
    if (i < (long)64 * V_) {
        int p = (int)(i / V_);
        int v = (int)(i - (long)p * V_);
        out[(size_t)p * L_ * V_ + v] = (v == 1) ? 1.0f : 0.0f;
    }
}

// gather embeddings -> g_A fp32 (for gi GEMM) and g_Ahi/g_Alo fp16
__global__ void k_gather(const int* __restrict__ input, const float* __restrict__ emb) {
    int row = blockIdx.x;
    int s = row / ROWS_PER_S;
    int rr = row - s * ROWS_PER_S;
    int t = rr >> 4;
    int b = rr & 15;
    int tok = input[(b * S_ + s) * L_ + t];
    float4 v = ((const float4*)(emb + (size_t)tok * E_))[threadIdx.x];
    ((float4*)(g_A + (size_t)row * 1024))[threadIdx.x] = v;
    uint2 hi, lo;
    fp16_split4(v, hi, lo);
    *(uint2*)(g_Ahi + (size_t)row * 1024 + threadIdx.x * 4) = hi;
    *(uint2*)(g_Alo + (size_t)row * 1024 + threadIdx.x * 4) = lo;
}

// fc_W -> g_Wh (cols<1024) and g_Wc (cols 1024:1536), fp16; also reset barrier
__global__ void k_wsplit(const float* __restrict__ fc_W) {
    long idx = (long)blockIdx.x * 256 + threadIdx.x;   // one float4 each
    if (idx == 0) g_bar = 0;
    if (idx >= (long)V_ * 384) return;
    int row = (int)(idx / 384);
    int c4 = (int)(idx - (long)row * 384);
    int col = c4 * 4;
    float4 v = *(const float4*)(fc_W + (size_t)row * G3 + col);
    uint2 h = fp16_pack4(v);
    if (col < 1024)
        *(uint2*)(g_Wh + (size_t)row * 1024 + col) = h;
    else
        *(uint2*)(g_Wc + (size_t)row * 512 + (col - 1024)) = h;
}

// agg (64 x 512) -> fp16 hi/lo split (rows 64..127 remain zero)
__global__ void k_cprep(const float* __restrict__ agg) {
    int row = blockIdx.x;                 // 0..63
    float4 v = ((const float4*)(agg + (size_t)row * 512))[threadIdx.x];
    uint2 hi, lo;
    fp16_split4(v, hi, lo);
    *(uint2*)(g_Chi + (size_t)row * 512 + threadIdx.x * 4) = hi;
    *(uint2*)(g_Clo + (size_t)row * 512 + threadIdx.x * 4) = lo;
}

// gictx[s,b,g] = ctx[s,b,:] . W_ih[s,g,512:] + b_ih[s,g]
__global__ void k_ctx_gi(const float* __restrict__ hidden,
                         const float* __restrict__ agg,
                         const float* __restrict__ W_ih,
                         const float* __restrict__ b_ih) {
    int w = blockIdx.x * 8 + (threadIdx.x >> 5);
    int lane = threadIdx.x & 31;
    int s = w / G3;
    int g = w - s * G3;
    const float* ctx = (s == 0) ? agg : (hidden + (size_t)s * B_ * H_);
    const float* wrow = W_ih + ((size_t)(s * G3) + g) * 1024 + 512;
    float acc[16];
#pragma unroll
    for (int b = 0; b < 16; b++) acc[b] = 0.0f;
    for (int d = lane; d < 512; d += 32) {
        float wv = wrow[d];
#pragma unroll
        for (int b = 0; b < 16; b++) acc[b] += wv * ctx[b * 512 + d];
    }
    float res = 0.0f;
#pragma unroll
    for (int b = 0; b < 16; b++) {
        float v = acc[b];
#pragma unroll
        for (int off = 16; off; off >>= 1) v += __shfl_xor_sync(0xffffffffu, v, off);
        if (lane == b) res = v;
    }
    if (lane < 16)
        g_gictx[(size_t)(s * 16 + lane) * G3 + g] = res + b_ih[s * G3 + g];
}

// ===================== SIMT GEMM: gi emb part =====================
__global__ void __launch_bounds__(256) k_gemm0(const float* __restrict__ W_ih) {
    int s = blockIdx.z;
    const float* A = g_A + (size_t)s * ROWS_PER_S * 1024;
    const float* B = W_ih + (size_t)s * G3 * 1024;
    const int lda = 1024, ldb = 1024, M = ROWS_PER_S, K = 512;

    __shared__ float As[16][128];
    __shared__ float Bs[16][128];

    int tid = threadIdx.x;
    int m0 = blockIdx.y * 128;
    int n0 = blockIdx.x * 128;
    int trow = tid >> 4;
    int tcol = tid & 15;

    float acc[8][8];
#pragma unroll
    for (int i = 0; i < 8; i++)
#pragma unroll
        for (int j = 0; j < 8; j++) acc[i][j] = 0.0f;

    for (int k0 = 0; k0 < K; k0 += 16) {
#pragma unroll
        for (int it = 0; it < 2; it++) {
            int i = tid + it * 256;
            int mm = i >> 2;
            int kk = (i & 3) << 2;
            float4 av = make_float4(0.f, 0.f, 0.f, 0.f);
            if (m0 + mm < M)
                av = *(const float4*)(A + (size_t)(m0 + mm) * lda + k0 + kk);
            As[kk + 0][mm] = av.x; As[kk + 1][mm] = av.y;
            As[kk + 2][mm] = av.z; As[kk + 3][mm] = av.w;
            float4 bv = *(const float4*)(B + (size_t)(n0 + mm) * ldb + k0 + kk);
            Bs[kk + 0][mm] = bv.x; Bs[kk + 1][mm] = bv.y;
            Bs[kk + 2][mm] = bv.z; Bs[kk + 3][mm] = bv.w;
        }
        __syncthreads();
#pragma unroll
        for (int kk = 0; kk < 16; kk++) {
            float a[8], bb[8];
            *(float4*)&a[0]  = *(const float4*)&As[kk][trow * 8];
            *(float4*)&a[4]  = *(const float4*)&As[kk][trow * 8 + 4];
            *(float4*)&bb[0] = *(const float4*)&Bs[kk][tcol * 8];
            *(float4*)&bb[4] = *(const float4*)&Bs[kk][tcol * 8 + 4];
#pragma unroll
            for (int i = 0; i < 8; i++)
#pragma unroll
                for (int j = 0; j < 8; j++) acc[i][j] += a[i] * bb[j];
        }
        __syncthreads();
    }

    int rbase = m0 + trow * 8;
    int cbase = n0 + tcol * 8;
#pragma unroll
    for (int i = 0; i < 8; i++) {
        int r = rbase + i;
        if (r < ROWS_PER_S) {
            int b = r & 15;
            const float* add = g_gictx + (size_t)(s * 16 + b) * G3 + cbase;
            float* dst = g_gi + (size_t)(s * ROWS_PER_S + r) * G3 + cbase;
#pragma unroll
            for (int j = 0; j < 8; j++) dst[j] = acc[i][j] + add[j];
        }
    }
}

// ===================== persistent GRU scan =====================
#define WPAD 1544
#define SCAN_SMEM ((16 * WPAD + 16 * 516) * 4)

__global__ void __launch_bounds__(256) k_gru_scan(
    const float* __restrict__ hidden, const float* __restrict__ W_hh,
    const float* __restrict__ b_hh) {
    extern __shared__ float sm[];
    float* Wsm = sm;                 // [16][WPAD]
    float* hsm = sm + 16 * WPAD;     // [16][516]
    int bid = blockIdx.x;
    int s = bid >> 5, jt = bid & 31;
    int tid = threadIdx.x;
    int b = tid & 15, jl = tid >> 4;
    int j = jt * 16 + jl;

    for (int i = tid; i < 16 * 3 * 128; i += 256) {
        int jj = i / 384;
        int rem = i - jj * 384;
        int gate = rem >> 7;
        int d4 = rem & 127;
        float4 v = *(const float4*)(W_hh +
            ((size_t)(s * G3 + gate * 512 + jt * 16 + jj)) * 512 + d4 * 4);
        *(float4*)(Wsm + jj * WPAD + gate * 512 + d4 * 4) = v;
    }
    float bhr = b_hh[s * G3 + j];
    float bhz = b_hh[s * G3 + 512 + j];
    float bhn = b_hh[s * G3 + 1024 + j];
    __syncthreads();

    const float4* wr = (const float4*)(Wsm + jl * WPAD);
    const float4* wz = (const float4*)(Wsm + jl * WPAD + 512);
    const float4* wn = (const float4*)(Wsm + jl * WPAD + 1024);

    for (int t = 0; t < T_; t++) {
        const float* hin = (t == 0) ? (hidden + (size_t)s * B_ * H_)
                                    : (g_h[t & 1] + (size_t)s * B_ * H_);
        for (int i = tid; i < B_ * H_; i += 256)
            hsm[(i >> 9) * 516 + (i & 511)] = hin[i];
        __syncthreads();

        const float4* h4 = (const float4*)(hsm + b * 516);
        float rx = 0, ry = 0, rz = 0, rw = 0;
        float zx = 0, zy = 0, zz = 0, zw = 0;
        float nx = 0, ny = 0, nz = 0, nw = 0;
#pragma unroll 8
        for (int d = 0; d < 128; d++) {
            float4 h = h4[d];
            float4 a = wr[d];
            float4 c = wz[d];
            float4 e = wn[d];
            rx += h.x * a.x; ry += h.y * a.y; rz += h.z * a.z; rw += h.w * a.w;
            zx += h.x * c.x; zy += h.y * c.y; zz += h.z * c.z; zw += h.w * c.w;
            nx += h.x * e.x; ny += h.y * e.y; nz += h.z * e.z; nw += h.w * e.w;
        }
        float ghr = (rx + ry) + (rz + rw) + bhr;
        float ghz = (zx + zy) + (zz + zw) + bhz;
        float ghn = (nx + ny) + (nz + nw) + bhn;

        int row = s * ROWS_PER_S + t * 16 + b;
        const float* gi = g_gi + (size_t)row * G3;
        float r = sigmoidf_(gi[j] + ghr);
        float z = sigmoidf_(gi[512 + j] + ghz);
        float n = tanhf(gi[1024 + j] + r * ghn);
        float hold = hsm[b * 516 + j];
        float hnew = (1.0f - z) * n + z * hold;

        g_h[(t + 1) & 1][((size_t)s * 16 + b) * 512 + j] = hnew;
        __half hh = __float2half(hnew);
        __half hl = __float2half(hnew - __half2float(hh));
        g_Ahi[(size_t)row * 1024 + 512 + j] = hh;
        g_Alo[(size_t)row * 1024 + 512 + j] = hl;

        __threadfence();
        __syncthreads();
        if (tid == 0) {
            atomicAdd(&g_bar, 1u);
            unsigned target = 128u * (unsigned)(t + 1);
            while (*((volatile unsigned*)&g_bar) < target) { }
        }
        __syncthreads();
        __threadfence();
    }
}

// ===================== fp16 2-pass mma GEMM =====================
// MODE 2: out[1472,32000] = A(hi+lo)[.,1024] @ Wh^T + ctxlogit  (scatter)
// MODE 1: g_ctxlogit[64,32000] = C(hi+lo)[.,512] @ Wc^T + fc_b
#define STAGE3 24576       // Ahi 8K | Alo 8K | B 8K
#define FC_SMEM (4 * STAGE3)

template <int MODE>
__global__ void __launch_bounds__(128, 2) k_fc(
    const __half* __restrict__ Ah, const __half* __restrict__ Al,
    const __half* __restrict__ Bw, const float* __restrict__ bias,
    float* __restrict__ out) {
    constexpr int KCH = (MODE == 2) ? 32 : 16;   // chunks of K=32
    constexpr int LDA = (MODE == 2) ? 1024 : 512;
    constexpr int LDB = (MODE == 2) ? 1024 : 512;

    extern __shared__ __align__(128) char sm_raw[];
    const uint32_t smem_base = smem_u32(sm_raw);
    const int tid = threadIdx.x;
    const int lane = tid & 31;
    const int w = tid >> 5;
    const int wm = w >> 1;      // 0..1
    const int wn = w & 1;       // 0..1
    const int m0 = blockIdx.x * 128;
    const int n0 = blockIdx.y * 128;

    float acc[4][8][4];
#pragma unroll
    for (int mt = 0; mt < 4; mt++)
#pragma unroll
        for (int nt = 0; nt < 8; nt++)
#pragma unroll
            for (int k = 0; k < 4; k++) acc[mt][nt][k] = 0.0f;

    auto load_stage = [&](int c) {
        int kk = c << 5;
        uint32_t st = smem_base + (c & 3) * STAGE3;
        const __half* ah = Ah + (size_t)m0 * LDA + kk;
        const __half* al = Al + (size_t)m0 * LDA + kk;
        const __half* bw = Bw + (size_t)n0 * LDB + kk;
#pragma unroll
        for (int it = 0; it < 4; it++) {
            int idx = tid + it * 128;
            int r = idx >> 2, g = idx & 3;
            uint32_t doff = r * 64 + ((g ^ ((r >> 1) & 3)) << 4);
            size_t soff = (size_t)r * LDA + g * 8;
            CP_ASYNC16(st + doff, ah + soff);
            CP_ASYNC16(st + 8192 + doff, al + soff);
            CP_ASYNC16(st + 16384 + doff, bw + (size_t)r * LDB + g * 8);
        }
    };

    load_stage(0); CP_COMMIT();
    load_stage(1); CP_COMMIT();
    load_stage(2); CP_COMMIT();

    const int arow_b = wm * 64 + (lane & 15);
    const int aseg_b = lane >> 4;
    const int brow_b = wn * 64 + (lane & 7) + ((lane >> 4) << 3);
    const int bseg_b = (lane >> 3) & 1;

    for (int c = 0; c < KCH; c++) {
        int pend = ((KCH - 1 - c) < 2) ? (KCH - 1 - c) : 2;
        if (pend == 2)      asm volatile("cp.async.wait_group 2;" ::: "memory");
        else if (pend == 1) asm volatile("cp.async.wait_group 1;" ::: "memory");
        else                asm volatile("cp.async.wait_group 0;" ::: "memory");
        __syncthreads();
        if (c + 3 < KCH) { load_stage(c + 3); CP_COMMIT(); }

        uint32_t sa = smem_base + (c & 3) * STAGE3;
        uint32_t sb = sa + 16384;
#pragma unroll
        for (int ks = 0; ks < 2; ks++) {
            uint32_t ra_h[4][4], ra_l[4][4];
#pragma unroll
            for (int mt = 0; mt < 4; mt++) {
                int r = arow_b + mt * 16;
                int seg = 2 * ks + aseg_b;
                uint32_t doff = r * 64 + ((seg ^ ((r >> 1) & 3)) << 4);
                LDSM4(ra_h[mt][0], ra_h[mt][1], ra_h[mt][2], ra_h[mt][3], sa + doff);
                LDSM4(ra_l[mt][0], ra_l[mt][1], ra_l[mt][2], ra_l[mt][3], sa + 8192 + doff);
            }
#pragma unroll
            for (int nt2 = 0; nt2 < 4; nt2++) {
                int r = brow_b + nt2 * 16;
                int seg = 2 * ks + bseg_b;
                uint32_t doff = r * 64 + ((seg ^ ((r >> 1) & 3)) << 4);
                uint32_t rb[4];
                LDSM4(rb[0], rb[1], rb[2], rb[3], sb + doff);
#pragma unroll
                for (int mt = 0; mt < 4; mt++) {
                    MMA16816H(acc[mt][nt2 * 2 + 0], ra_h[mt], rb[0], rb[1]);
                    MMA16816H(acc[mt][nt2 * 2 + 1], ra_h[mt], rb[2], rb[3]);
                }
#pragma unroll
                for (int mt = 0; mt < 4; mt++) {
                    MMA16816H(acc[mt][nt2 * 2 + 0], ra_l[mt], rb[0], rb[1]);
                    MMA16816H(acc[mt][nt2 * 2 + 1], ra_l[mt], rb[2], rb[3]);
                }
            }
        }
        __syncthreads();
    }

    // epilogue
#pragma unroll
    for (int mt = 0; mt < 4; mt++) {
#pragma unroll
        for (int half = 0; half < 2; half++) {
            int R = m0 + wm * 64 + mt * 16 + (lane >> 2) + half * 8;
            if (MODE == 2) {
                if (R >= ROWS) continue;
                int s2 = R / ROWS_PER_S;
                int rr = R - s2 * ROWS_PER_S;
                int tt = rr >> 4;
                int b = rr & 15;
                float* dst = out + ((size_t)((b * S_ + s2) * L_ + tt + 1)) * V_;
                const float* ctx = g_ctxlogit + (size_t)(s2 * 16 + b) * V_;
#pragma unroll
                for (int nt = 0; nt < 8; nt++) {
                    int col = n0 + wn * 64 + nt * 8 + (lane & 3) * 2;
                    float2 cv = *(const float2*)(ctx + col);
                    float2 o;
                    o.x = acc[mt][nt][half * 2 + 0] + cv.x;
                    o.y = acc[mt][nt][half * 2 + 1] + cv.y;
                    *(float2*)(dst + col) = o;
                }
            } else {
                if (R >= 64) continue;
                float* dst = g_ctxlogit + (size_t)R * V_;
#pragma unroll
                for (int nt = 0; nt < 8; nt++) {
                    int col = n0 + wn * 64 + nt * 8 + (lane & 3) * 2;
                    float2 bv = *(const float2*)(bias + col);
                    float2 o;
                    o.x = acc[mt][nt][half * 2 + 0] + bv.x;
                    o.y = acc[mt][nt][half * 2 + 1] + bv.y;
                    *(float2*)(dst + col) = o;
                }
            }
        }
    }
}

// ===================== launch =====================
extern "C" void kernel_launch(void* const* d_in, const int* in_sizes, int n_in,
                              void* d_out, int out_size) {
    const int*   input  = (const int*)d_in[0];
    const float* hidden = (const float*)d_in[1];
    const float* agg    = (const float*)d_in[2];
    const float* emb    = (const float*)d_in[3];
    const float* W_ih   = (const float*)d_in[4];
    const float* W_hh   = (const float*)d_in[5];
    const float* b_ih   = (const float*)d_in[6];
    const float* b_hh   = (const float*)d_in[7];
    const float* fc_W   = (const float*)d_in[8];
    const float* fc_b   = (const float*)d_in[9];
    float* out = (float*)d_out;

    cudaFuncSetAttribute(k_fc<1>, cudaFuncAttributeMaxDynamicSharedMemorySize, FC_SMEM);
    cudaFuncSetAttribute(k_fc<2>, cudaFuncAttributeMaxDynamicSharedMemorySize, FC_SMEM);
    cudaFuncSetAttribute(k_gru_scan, cudaFuncAttributeMaxDynamicSharedMemorySize, SCAN_SMEM);

    __half* Ah; cudaGetSymbolAddress((void**)&Ah, g_Ahi);
    __half* Al; cudaGetSymbolAddress((void**)&Al, g_Alo);
    __half* Wh; cudaGetSymbolAddress((void**)&Wh, g_Wh);
    __half* Wc; cudaGetSymbolAddress((void**)&Wc, g_Wc);
    __half* Ch; cudaGetSymbolAddress((void**)&Ch, g_Chi);
    __half* Cl; cudaGetSymbolAddress((void**)&Cl, g_Clo);

    k_onehot<<<(64 * V_ + 255) / 256, 256>>>(out);
    k_gather<<<ROWS, 128>>>(input, emb);
    k_wsplit<<<(int)(((long)V_ * 384 + 255) / 256), 256>>>(fc_W);
    k_cprep<<<64, 128>>>(agg);
    k_ctx_gi<<<(S_ * G3) / 8, 256>>>(hidden, agg, W_ih, b_ih);
    k_gemm0<<<dim3(12, 3, 4), 256>>>(W_ih);
    k_gru_scan<<<128, 256, SCAN_SMEM>>>(hidden, W_hh, b_hh);
    k_fc<1><<<dim3(1, V_ / 128), 128, FC_SMEM>>>(Ch, Cl, Wc, fc_b, nullptr);
    k_fc<2><<<dim3(MPAD / 128, V_ / 128), 128, FC_SMEM>>>(Ah, Al, Wh, nullptr, out);
}